// round 1
// baseline (speedup 1.0000x reference)
#include <cuda_runtime.h>
#include <cuda_bf16.h>
#include <stdint.h>

// ---------------------------------------------------------------------------
// ConvAttention: edge attention over a graph
//   q,k,v = per-head 16x16 projections of x (100k x 64)
//   alpha[p,h] = sum_d q_i[p,h,d]*w[p,h,d]*k_j[p,h,d] / 4 * mask[p]*phi[p]
//   out[n]   += alpha[p] * v_j[p]  segment-summed over sorted idx_i
// ---------------------------------------------------------------------------

#define F 64
#define H 4
#define D 16
#define MAX_NODES 100000

// scratch (static __device__ arrays: allowed; no cudaMalloc)
__device__ float g_Q[MAX_NODES * F];
__device__ float g_K[MAX_NODES * F];
__device__ float g_V[MAX_NODES * F];
__device__ int   g_start[MAX_NODES + 1];
__device__ int   g_is64;

// ---------------------------------------------------------------------------
// Probe: detect whether idx buffers are int64 or int32.
// Values are in [0, 100000) < 2^31, so in int64 little-endian layout every
// odd 32-bit word is zero. idx_j is random (not sorted), so 16 consecutive
// odd-word zeros cannot happen for int32 data.
// ---------------------------------------------------------------------------
__global__ void probe_kernel(const unsigned* idxj_words) {
    bool is64 = true;
    #pragma unroll
    for (int i = 0; i < 16; i++) {
        if (idxj_words[2 * i + 1] != 0u) is64 = false;
    }
    g_is64 = is64 ? 1 : 0;
}

__device__ __forceinline__ int load_idx(const void* p, int i, bool is64) {
    if (is64) return (int)((const long long*)p)[i];
    return ((const int*)p)[i];
}

// ---------------------------------------------------------------------------
// Projection: Q/K/V[n, h*16+e] = sum_d x[n, h*16+d] * W*(h, d, e)
// One thread per output element (n, f).
// ---------------------------------------------------------------------------
__global__ __launch_bounds__(256)
void proj_kernel(const float* __restrict__ x,
                 const float* __restrict__ Wq,
                 const float* __restrict__ Wk,
                 const float* __restrict__ Wv,
                 int n_nodes)
{
    int gid = blockIdx.x * blockDim.x + threadIdx.x;
    if (gid >= n_nodes * F) return;
    int n = gid / F;
    int f = gid % F;
    int h = f / D;
    int e = f % D;

    const float* xr = x + (size_t)n * F + h * D;   // 16 inputs of this head
    const float* wq = Wq + h * D * D + e;          // stride D over d
    const float* wk = Wk + h * D * D + e;
    const float* wv = Wv + h * D * D + e;

    float q = 0.f, k = 0.f, v = 0.f;
    #pragma unroll
    for (int d = 0; d < D; d++) {
        float xv = xr[d];
        q = fmaf(xv, wq[d * D], q);
        k = fmaf(xv, wk[d * D], k);
        v = fmaf(xv, wv[d * D], v);
    }
    g_Q[gid] = q;
    g_K[gid] = k;
    g_V[gid] = v;
}

// ---------------------------------------------------------------------------
// Segment starts: start[n] = lower_bound(idx_i, n), n in [0, n_nodes]
// ---------------------------------------------------------------------------
__global__ __launch_bounds__(256)
void seg_start_kernel(const void* __restrict__ idx_i, int n_pairs, int n_nodes)
{
    int n = blockIdx.x * blockDim.x + threadIdx.x;
    if (n > n_nodes) return;
    bool is64 = (g_is64 != 0);
    int lo = 0, hi = n_pairs;
    while (lo < hi) {
        int mid = (lo + hi) >> 1;
        int v = load_idx(idx_i, mid, is64);
        if (v < n) lo = mid + 1; else hi = mid;
    }
    g_start[n] = lo;
}

// ---------------------------------------------------------------------------
// Main: one warp per destination node. Lane t owns features 2t, 2t+1
// (both inside head t/8). alpha reduction = 3 shfl.bfly within 8-lane group.
// ---------------------------------------------------------------------------
__global__ __launch_bounds__(256)
void attn_kernel(const float* __restrict__ w_ij,
                 const float* __restrict__ phi,
                 const float* __restrict__ mask,
                 const void*  __restrict__ idx_j,
                 float* __restrict__ out,
                 int n_nodes)
{
    int warp = (blockIdx.x * blockDim.x + threadIdx.x) >> 5;
    int lane = threadIdx.x & 31;
    if (warp >= n_nodes) return;

    bool is64 = (g_is64 != 0);
    int fo = lane * 2;

    float2 q = *(const float2*)&g_Q[(size_t)warp * F + fo];
    float2 acc = make_float2(0.f, 0.f);

    int s = g_start[warp];
    int e = g_start[warp + 1];

    for (int p = s; p < e; p++) {
        int j = load_idx(idx_j, p, is64);
        // streaming loads (evict-first): don't thrash L2-resident K/V
        float2 w = __ldcs((const float2*)&w_ij[(size_t)p * F + fo]);
        float  sc = __ldcs(&mask[p]) * __ldcs(&phi[p]);
        float2 k = *(const float2*)&g_K[(size_t)j * F + fo];
        float2 v = *(const float2*)&g_V[(size_t)j * F + fo];

        float partial = q.x * w.x * k.x + q.y * w.y * k.y;
        partial += __shfl_xor_sync(0xffffffffu, partial, 1);
        partial += __shfl_xor_sync(0xffffffffu, partial, 2);
        partial += __shfl_xor_sync(0xffffffffu, partial, 4);

        float alpha = partial * 0.25f * sc;   // 1/sqrt(16) = 0.25
        acc.x = fmaf(alpha, v.x, acc.x);
        acc.y = fmaf(alpha, v.y, acc.y);
    }

    *(float2*)&out[(size_t)warp * F + fo] = acc;
}

// ---------------------------------------------------------------------------
// Launch
//   inputs (metadata order): x, w_ij, phi_r_cut, pair_mask, Wq, Wk, Wv,
//                            idx_i, idx_j
// ---------------------------------------------------------------------------
extern "C" void kernel_launch(void* const* d_in, const int* in_sizes, int n_in,
                              void* d_out, int out_size)
{
    const float* x     = (const float*)d_in[0];
    const float* w_ij  = (const float*)d_in[1];
    const float* phi   = (const float*)d_in[2];
    const float* mask  = (const float*)d_in[3];
    const float* Wq    = (const float*)d_in[4];
    const float* Wk    = (const float*)d_in[5];
    const float* Wv    = (const float*)d_in[6];
    const void*  idx_i = d_in[7];
    const void*  idx_j = d_in[8];
    float* out = (float*)d_out;

    int n_nodes = in_sizes[0] / F;       // 100000
    int n_pairs = in_sizes[2];           // phi_r_cut element count = 1600000

    probe_kernel<<<1, 1>>>((const unsigned*)idx_j);

    int proj_blocks = (n_nodes * F + 255) / 256;
    proj_kernel<<<proj_blocks, 256>>>(x, Wq, Wk, Wv, n_nodes);

    int seg_blocks = (n_nodes + 1 + 255) / 256;
    seg_start_kernel<<<seg_blocks, 256>>>(idx_i, n_pairs, n_nodes);

    int attn_blocks = (n_nodes + 7) / 8;   // 8 warps per block, 1 warp/node
    attn_kernel<<<attn_blocks, 256>>>(w_ij, phi, mask, idx_j, out, n_nodes);
}

// round 2
// speedup vs baseline: 1.0733x; 1.0733x over previous
#include <cuda_runtime.h>
#include <cuda_bf16.h>
#include <stdint.h>

// ---------------------------------------------------------------------------
// ConvAttention, two-phase:
//   phase A (pair-parallel): alpha[p,h] = (q_i . w . k_j)/4 * mask*phi
//   phase B (warp-per-node): out[i]    = sum_p alpha[p,h] * v_j[p]
// ---------------------------------------------------------------------------

#define F 64
#define H 4
#define D 16
#define MAX_NODES 100000
#define MAX_PAIRS 1600000

__device__ float g_Q[MAX_NODES * F];
__device__ float g_K[MAX_NODES * F];
__device__ float g_V[MAX_NODES * F];
__device__ float g_alpha[MAX_PAIRS * H];
__device__ int   g_start[MAX_NODES + 1];
__device__ int   g_is64;

// ---------------------------------------------------------------------------
// Probe int64 vs int32 index layout (values < 2^31 => odd words zero if i64).
// ---------------------------------------------------------------------------
__global__ void probe_kernel(const unsigned* idxj_words) {
    bool is64 = true;
    #pragma unroll
    for (int i = 0; i < 16; i++)
        if (idxj_words[2 * i + 1] != 0u) is64 = false;
    g_is64 = is64 ? 1 : 0;
}

__device__ __forceinline__ int load_idx(const void* p, int i, bool is64) {
    if (is64) return (int)((const long long*)p)[i];
    return ((const int*)p)[i];
}

// ---------------------------------------------------------------------------
// Projection: Q/K/V[n, h*16+e] = sum_d x[n, h*16+d] * W*(h,d,e)
// ---------------------------------------------------------------------------
__global__ __launch_bounds__(256)
void proj_kernel(const float* __restrict__ x,
                 const float* __restrict__ Wq,
                 const float* __restrict__ Wk,
                 const float* __restrict__ Wv,
                 int n_nodes)
{
    int gid = blockIdx.x * blockDim.x + threadIdx.x;
    if (gid >= n_nodes * F) return;
    int n = gid / F;
    int f = gid % F;
    int h = f / D;
    int e = f % D;

    const float* xr = x + (size_t)n * F + h * D;
    const float* wq = Wq + h * D * D + e;
    const float* wk = Wk + h * D * D + e;
    const float* wv = Wv + h * D * D + e;

    float q = 0.f, k = 0.f, v = 0.f;
    #pragma unroll
    for (int d = 0; d < D; d++) {
        float xv = xr[d];
        q = fmaf(xv, wq[d * D], q);
        k = fmaf(xv, wk[d * D], k);
        v = fmaf(xv, wv[d * D], v);
    }
    g_Q[gid] = q;
    g_K[gid] = k;
    g_V[gid] = v;
}

// ---------------------------------------------------------------------------
// Segment starts via binary search over sorted idx_i.
// ---------------------------------------------------------------------------
__global__ __launch_bounds__(256)
void seg_start_kernel(const void* __restrict__ idx_i, int n_pairs, int n_nodes)
{
    int n = blockIdx.x * blockDim.x + threadIdx.x;
    if (n > n_nodes) return;
    bool is64 = (g_is64 != 0);
    int lo = 0, hi = n_pairs;
    while (lo < hi) {
        int mid = (lo + hi) >> 1;
        int v = load_idx(idx_i, mid, is64);
        if (v < n) lo = mid + 1; else hi = mid;
    }
    g_start[n] = lo;
}

// ---------------------------------------------------------------------------
// Phase A: one thread per (pair, head). 12 independent 16B loads -> high MLP.
// ---------------------------------------------------------------------------
__global__ __launch_bounds__(256)
void alpha_kernel(const float* __restrict__ w_ij,
                  const float* __restrict__ phi,
                  const float* __restrict__ mask,
                  const void*  __restrict__ idx_i,
                  const void*  __restrict__ idx_j,
                  int n_pairs)
{
    int gid = blockIdx.x * blockDim.x + threadIdx.x;
    if (gid >= n_pairs * H) return;
    int p = gid >> 2;
    int h = gid & 3;
    bool is64 = (g_is64 != 0);

    int i = load_idx(idx_i, p, is64);
    int j = load_idx(idx_j, p, is64);

    const float4* wp = (const float4*)&w_ij[(size_t)p * F + h * D];
    const float4* qp = (const float4*)&g_Q[(size_t)i * F + h * D];
    const float4* kp = (const float4*)&g_K[(size_t)j * F + h * D];

    float s = 0.f;
    #pragma unroll
    for (int c = 0; c < 4; c++) {
        float4 w = __ldcs(&wp[c]);   // streaming: don't thrash L2-resident K/V
        float4 q = qp[c];
        float4 k = kp[c];
        s = fmaf(w.x * q.x, k.x, s);
        s = fmaf(w.y * q.y, k.y, s);
        s = fmaf(w.z * q.z, k.z, s);
        s = fmaf(w.w * q.w, k.w, s);
    }
    g_alpha[gid] = s * 0.25f * mask[p] * phi[p];   // 1/sqrt(16)=0.25
}

// ---------------------------------------------------------------------------
// Phase B: warp per destination node; lane owns features 2t,2t+1.
// Unrolled by 4 so idx/alpha/v loads batch -> MLP ~4 per warp.
// ---------------------------------------------------------------------------
__global__ __launch_bounds__(256)
void scatter_kernel(const void* __restrict__ idx_j,
                    float* __restrict__ out,
                    int n_nodes)
{
    int warp = (blockIdx.x * blockDim.x + threadIdx.x) >> 5;
    int lane = threadIdx.x & 31;
    if (warp >= n_nodes) return;
    bool is64 = (g_is64 != 0);

    int fo   = lane * 2;
    int head = lane >> 3;

    float2 acc = make_float2(0.f, 0.f);
    int s = g_start[warp];
    int e = g_start[warp + 1];

    int p = s;
    for (; p + 4 <= e; p += 4) {
        int j0 = load_idx(idx_j, p + 0, is64);
        int j1 = load_idx(idx_j, p + 1, is64);
        int j2 = load_idx(idx_j, p + 2, is64);
        int j3 = load_idx(idx_j, p + 3, is64);
        float a0 = g_alpha[(size_t)(p + 0) * H + head];
        float a1 = g_alpha[(size_t)(p + 1) * H + head];
        float a2 = g_alpha[(size_t)(p + 2) * H + head];
        float a3 = g_alpha[(size_t)(p + 3) * H + head];
        float2 v0 = *(const float2*)&g_V[(size_t)j0 * F + fo];
        float2 v1 = *(const float2*)&g_V[(size_t)j1 * F + fo];
        float2 v2 = *(const float2*)&g_V[(size_t)j2 * F + fo];
        float2 v3 = *(const float2*)&g_V[(size_t)j3 * F + fo];
        acc.x = fmaf(a0, v0.x, acc.x);  acc.y = fmaf(a0, v0.y, acc.y);
        acc.x = fmaf(a1, v1.x, acc.x);  acc.y = fmaf(a1, v1.y, acc.y);
        acc.x = fmaf(a2, v2.x, acc.x);  acc.y = fmaf(a2, v2.y, acc.y);
        acc.x = fmaf(a3, v3.x, acc.x);  acc.y = fmaf(a3, v3.y, acc.y);
    }
    for (; p < e; p++) {
        int j = load_idx(idx_j, p, is64);
        float a = g_alpha[(size_t)p * H + head];
        float2 v = *(const float2*)&g_V[(size_t)j * F + fo];
        acc.x = fmaf(a, v.x, acc.x);
        acc.y = fmaf(a, v.y, acc.y);
    }

    *(float2*)&out[(size_t)warp * F + fo] = acc;
}

// ---------------------------------------------------------------------------
// Launch: x, w_ij, phi_r_cut, pair_mask, Wq, Wk, Wv, idx_i, idx_j
// ---------------------------------------------------------------------------
extern "C" void kernel_launch(void* const* d_in, const int* in_sizes, int n_in,
                              void* d_out, int out_size)
{
    const float* x     = (const float*)d_in[0];
    const float* w_ij  = (const float*)d_in[1];
    const float* phi   = (const float*)d_in[2];
    const float* mask  = (const float*)d_in[3];
    const float* Wq    = (const float*)d_in[4];
    const float* Wk    = (const float*)d_in[5];
    const float* Wv    = (const float*)d_in[6];
    const void*  idx_i = d_in[7];
    const void*  idx_j = d_in[8];
    float* out = (float*)d_out;

    int n_nodes = in_sizes[0] / F;
    int n_pairs = in_sizes[2];

    probe_kernel<<<1, 1>>>((const unsigned*)idx_j);

    int proj_blocks = (n_nodes * F + 255) / 256;
    proj_kernel<<<proj_blocks, 256>>>(x, Wq, Wk, Wv, n_nodes);

    int seg_blocks = (n_nodes + 1 + 255) / 256;
    seg_start_kernel<<<seg_blocks, 256>>>(idx_i, n_pairs, n_nodes);

    int alpha_blocks = (n_pairs * H + 255) / 256;
    alpha_kernel<<<alpha_blocks, 256>>>(w_ij, phi, mask, idx_i, idx_j, n_pairs);

    int scat_blocks = (n_nodes + 7) / 8;
    scatter_kernel<<<scat_blocks, 256>>>(idx_j, out, n_nodes);
}

// round 3
// speedup vs baseline: 1.0822x; 1.0083x over previous
#include <cuda_runtime.h>
#include <cuda_bf16.h>
#include <stdint.h>

#define F 64
#define H 4
#define D 16
#define MAX_NODES 100000
#define MAX_PAIRS 1600000

__device__ float g_Q[MAX_NODES * F];
__device__ float g_K[MAX_NODES * F];
__device__ float g_V[MAX_NODES * F];
__device__ float g_alpha[MAX_PAIRS * H];
__device__ int   g_ii[MAX_PAIRS];
__device__ int   g_jj[MAX_PAIRS];
__device__ int   g_start[MAX_NODES + 1];
__device__ int   g_is64;

// ---------------------------------------------------------------------------
// Probe int64 vs int32 index layout (values < 2^31 => odd words zero if i64).
// ---------------------------------------------------------------------------
__global__ void probe_kernel(const unsigned* idxj_words) {
    bool is64 = true;
    #pragma unroll
    for (int i = 0; i < 16; i++)
        if (idxj_words[2 * i + 1] != 0u) is64 = false;
    g_is64 = is64 ? 1 : 0;
}

// ---------------------------------------------------------------------------
// Convert idx arrays to int32 scratch once.
// ---------------------------------------------------------------------------
__global__ __launch_bounds__(256)
void conv_idx_kernel(const void* __restrict__ idx_i,
                     const void* __restrict__ idx_j, int n_pairs)
{
    int p = blockIdx.x * blockDim.x + threadIdx.x;
    if (p >= n_pairs) return;
    if (g_is64) {
        g_ii[p] = (int)((const long long*)idx_i)[p];
        g_jj[p] = (int)((const long long*)idx_j)[p];
    } else {
        g_ii[p] = ((const int*)idx_i)[p];
        g_jj[p] = ((const int*)idx_j)[p];
    }
}

// ---------------------------------------------------------------------------
// Projection: thread owns fixed (h,e); W columns live in registers;
// grid-stride over nodes (4 nodes per block-iteration).
// ---------------------------------------------------------------------------
__global__ __launch_bounds__(256)
void proj_kernel(const float* __restrict__ x,
                 const float* __restrict__ Wq,
                 const float* __restrict__ Wk,
                 const float* __restrict__ Wv,
                 int n_nodes)
{
    int f = threadIdx.x & 63;         // h*16 + e
    int h = f >> 4;
    int e = f & 15;
    int row = threadIdx.x >> 6;       // 0..3 nodes per block step

    float wq[D], wk[D], wv[D];
    #pragma unroll
    for (int d = 0; d < D; d++) {
        wq[d] = Wq[h * D * D + d * D + e];
        wk[d] = Wk[h * D * D + d * D + e];
        wv[d] = Wv[h * D * D + d * D + e];
    }

    for (int n = blockIdx.x * 4 + row; n < n_nodes; n += gridDim.x * 4) {
        const float* xr = x + (size_t)n * F + h * D;
        float q = 0.f, k = 0.f, v = 0.f;
        #pragma unroll
        for (int d = 0; d < D; d++) {
            float xv = xr[d];
            q = fmaf(xv, wq[d], q);
            k = fmaf(xv, wk[d], k);
            v = fmaf(xv, wv[d], v);
        }
        size_t o = (size_t)n * F + f;
        g_Q[o] = q;
        g_K[o] = k;
        g_V[o] = v;
    }
}

// ---------------------------------------------------------------------------
// Segment starts via binary search over sorted int32 idx_i.
// ---------------------------------------------------------------------------
__global__ __launch_bounds__(256)
void seg_start_kernel(int n_pairs, int n_nodes)
{
    int n = blockIdx.x * blockDim.x + threadIdx.x;
    if (n > n_nodes) return;
    int lo = 0, hi = n_pairs;
    while (lo < hi) {
        int mid = (lo + hi) >> 1;
        if (g_ii[mid] < n) lo = mid + 1; else hi = mid;
    }
    g_start[n] = lo;
}

// ---------------------------------------------------------------------------
// Phase A: lane = (pair%2)*16 + chunk. Each warp covers 2 pairs; every
// LDG.128 is 512B contiguous (minimum L1 wavefronts). Head sum via 2
// shfl_xor within 4-lane groups; leader lane writes alpha.
// ---------------------------------------------------------------------------
__global__ __launch_bounds__(256)
void alpha_kernel(const float* __restrict__ w_ij,
                  const float* __restrict__ phi,
                  const float* __restrict__ mask,
                  int n_pairs)
{
    int gid = blockIdx.x * blockDim.x + threadIdx.x;
    int p = gid >> 4;
    int c = gid & 15;
    if (p >= n_pairs) return;

    int i = g_ii[p];
    int j = g_jj[p];

    float4 w = __ldcs((const float4*)&w_ij[(size_t)p * F + c * 4]);
    float4 q = *(const float4*)&g_Q[(size_t)i * F + c * 4];
    float4 k = *(const float4*)&g_K[(size_t)j * F + c * 4];

    float s = w.x * q.x * k.x;
    s = fmaf(w.y * q.y, k.y, s);
    s = fmaf(w.z * q.z, k.z, s);
    s = fmaf(w.w * q.w, k.w, s);

    s += __shfl_xor_sync(0xffffffffu, s, 1);
    s += __shfl_xor_sync(0xffffffffu, s, 2);

    if ((c & 3) == 0) {
        float sc = mask[p] * phi[p] * 0.25f;   // 1/sqrt(16)
        g_alpha[(size_t)p * H + (c >> 2)] = s * sc;
    }
}

// ---------------------------------------------------------------------------
// Phase B: warp per destination node; lane owns features 2t,2t+1.
// Unrolled by 8 to batch idx/alpha/V loads (gather MLP ~8).
// ---------------------------------------------------------------------------
__global__ __launch_bounds__(256)
void scatter_kernel(float* __restrict__ out, int n_nodes)
{
    int warp = (blockIdx.x * blockDim.x + threadIdx.x) >> 5;
    int lane = threadIdx.x & 31;
    if (warp >= n_nodes) return;

    int fo   = lane * 2;
    int head = lane >> 3;

    float2 acc = make_float2(0.f, 0.f);
    int s = g_start[warp];
    int e = g_start[warp + 1];

    int p = s;
    for (; p + 8 <= e; p += 8) {
        int jj[8];
        float aa[8];
        float2 vv[8];
        #pragma unroll
        for (int u = 0; u < 8; u++) jj[u] = g_jj[p + u];
        #pragma unroll
        for (int u = 0; u < 8; u++) aa[u] = g_alpha[(size_t)(p + u) * H + head];
        #pragma unroll
        for (int u = 0; u < 8; u++) vv[u] = *(const float2*)&g_V[(size_t)jj[u] * F + fo];
        #pragma unroll
        for (int u = 0; u < 8; u++) {
            acc.x = fmaf(aa[u], vv[u].x, acc.x);
            acc.y = fmaf(aa[u], vv[u].y, acc.y);
        }
    }
    for (; p < e; p++) {
        int j = g_jj[p];
        float a = g_alpha[(size_t)p * H + head];
        float2 v = *(const float2*)&g_V[(size_t)j * F + fo];
        acc.x = fmaf(a, v.x, acc.x);
        acc.y = fmaf(a, v.y, acc.y);
    }

    *(float2*)&out[(size_t)warp * F + fo] = acc;
}

// ---------------------------------------------------------------------------
// Launch: x, w_ij, phi_r_cut, pair_mask, Wq, Wk, Wv, idx_i, idx_j
// ---------------------------------------------------------------------------
extern "C" void kernel_launch(void* const* d_in, const int* in_sizes, int n_in,
                              void* d_out, int out_size)
{
    const float* x     = (const float*)d_in[0];
    const float* w_ij  = (const float*)d_in[1];
    const float* phi   = (const float*)d_in[2];
    const float* mask  = (const float*)d_in[3];
    const float* Wq    = (const float*)d_in[4];
    const float* Wk    = (const float*)d_in[5];
    const float* Wv    = (const float*)d_in[6];
    const void*  idx_i = d_in[7];
    const void*  idx_j = d_in[8];
    float* out = (float*)d_out;

    int n_nodes = in_sizes[0] / F;
    int n_pairs = in_sizes[2];

    probe_kernel<<<1, 1>>>((const unsigned*)idx_j);

    conv_idx_kernel<<<(n_pairs + 255) / 256, 256>>>(idx_i, idx_j, n_pairs);

    proj_kernel<<<2048, 256>>>(x, Wq, Wk, Wv, n_nodes);

    seg_start_kernel<<<(n_nodes + 256) / 256, 256>>>(n_pairs, n_nodes);

    int alpha_blocks = (n_pairs * 16 + 255) / 256;
    alpha_kernel<<<alpha_blocks, 256>>>(w_ij, phi, mask, n_pairs);

    scatter_kernel<<<(n_nodes + 7) / 8, 256>>>(out, n_nodes);
}

// round 4
// speedup vs baseline: 1.1061x; 1.0221x over previous
#include <cuda_runtime.h>
#include <cuda_fp16.h>
#include <stdint.h>

#define F 64
#define H 4
#define D 16
#define MAX_NODES 100000
#define MAX_PAIRS 1600000

// fp16 projection scratch (halves L2 gather traffic + DRAM writes)
__device__ __half g_Qh[MAX_NODES * F];
__device__ __half g_Kh[MAX_NODES * F];
__device__ __half g_Vh[MAX_NODES * F];
__device__ float  g_alpha[MAX_PAIRS * H];
__device__ int    g_ii[MAX_PAIRS];
__device__ int    g_jj[MAX_PAIRS];
__device__ int    g_start[MAX_NODES + 1];
__device__ int    g_is64;

// ---------------------------------------------------------------------------
// Probe int64 vs int32 index layout (values < 2^31 => odd words zero if i64).
// ---------------------------------------------------------------------------
__global__ void probe_kernel(const unsigned* idxj_words) {
    bool is64 = true;
    #pragma unroll
    for (int i = 0; i < 16; i++)
        if (idxj_words[2 * i + 1] != 0u) is64 = false;
    g_is64 = is64 ? 1 : 0;
}

__device__ __forceinline__ int load_idx(const void* p, int i, bool is64) {
    if (is64) return (int)((const long long*)p)[i];
    return ((const int*)p)[i];
}

// ---------------------------------------------------------------------------
// Fused: convert idx to int32 + derive segment starts from sorted idx_i
// boundaries (no binary search).
// ---------------------------------------------------------------------------
__global__ __launch_bounds__(256)
void conv_seg_kernel(const void* __restrict__ idx_i,
                     const void* __restrict__ idx_j,
                     int n_pairs, int n_nodes)
{
    int p = blockIdx.x * blockDim.x + threadIdx.x;
    if (p >= n_pairs) return;
    bool is64 = (g_is64 != 0);

    int ip = load_idx(idx_i, p, is64);
    int jp = load_idx(idx_j, p, is64);
    g_ii[p] = ip;
    g_jj[p] = jp;

    int prev = (p == 0) ? -1 : load_idx(idx_i, p - 1, is64);
    for (int n = prev + 1; n <= ip; n++) g_start[n] = p;
    if (p == n_pairs - 1)
        for (int n = ip + 1; n <= n_nodes; n++) g_start[n] = n_pairs;
}

// ---------------------------------------------------------------------------
// Projection: block handles 4 nodes/iter; x staged in smem (coalesced),
// W columns in registers; writes fp16 Q/K/V.
// ---------------------------------------------------------------------------
__global__ __launch_bounds__(256)
void proj_kernel(const float* __restrict__ x,
                 const float* __restrict__ Wq,
                 const float* __restrict__ Wk,
                 const float* __restrict__ Wv,
                 int n_nodes)
{
    __shared__ float xs[4 * F];
    int f   = threadIdx.x & 63;   // h*16 + e
    int row = threadIdx.x >> 6;   // 0..3
    int h   = f >> 4;
    int e   = f & 15;

    float wq[D], wk[D], wv[D];
    #pragma unroll
    for (int d = 0; d < D; d++) {
        wq[d] = Wq[h * D * D + d * D + e];
        wk[d] = Wk[h * D * D + d * D + e];
        wv[d] = Wv[h * D * D + d * D + e];
    }

    for (int base = blockIdx.x * 4; base < n_nodes; base += gridDim.x * 4) {
        __syncthreads();
        size_t gidx = (size_t)base * F + threadIdx.x;
        if (gidx < (size_t)n_nodes * F) xs[threadIdx.x] = x[gidx];
        __syncthreads();

        int n = base + row;
        if (n < n_nodes) {
            const float* xr = &xs[row * F + h * D];
            float q = 0.f, k = 0.f, v = 0.f;
            #pragma unroll
            for (int d = 0; d < D; d++) {
                float xv = xr[d];
                q = fmaf(xv, wq[d], q);
                k = fmaf(xv, wk[d], k);
                v = fmaf(xv, wv[d], v);
            }
            size_t o = (size_t)n * F + f;
            g_Qh[o] = __float2half(q);
            g_Kh[o] = __float2half(k);
            g_Vh[o] = __float2half(v);
        }
    }
}

// ---------------------------------------------------------------------------
// Phase A: lane = (pair%2)*16 + chunk(0..15); chunk covers 4 features.
// w: 16B/lane contiguous; Q/K: 8B/lane (fp16) contiguous.
// Head sum via 2 shfl_xor within 4-lane groups.
// ---------------------------------------------------------------------------
__global__ __launch_bounds__(256)
void alpha_kernel(const float* __restrict__ w_ij,
                  const float* __restrict__ phi,
                  const float* __restrict__ mask,
                  int n_pairs)
{
    int gid = blockIdx.x * blockDim.x + threadIdx.x;
    int p = gid >> 4;
    int c = gid & 15;
    if (p >= n_pairs) return;

    int i = g_ii[p];
    int j = g_jj[p];

    float4 w = __ldcs((const float4*)&w_ij[(size_t)p * F + c * 4]);

    uint2 qr = *(const uint2*)&g_Qh[(size_t)i * F + c * 4];
    uint2 kr = *(const uint2*)&g_Kh[(size_t)j * F + c * 4];
    float2 q0 = __half22float2(*(const __half2*)&qr.x);
    float2 q1 = __half22float2(*(const __half2*)&qr.y);
    float2 k0 = __half22float2(*(const __half2*)&kr.x);
    float2 k1 = __half22float2(*(const __half2*)&kr.y);

    float s = w.x * q0.x * k0.x;
    s = fmaf(w.y * q0.y, k0.y, s);
    s = fmaf(w.z * q1.x, k1.x, s);
    s = fmaf(w.w * q1.y, k1.y, s);

    s += __shfl_xor_sync(0xffffffffu, s, 1);
    s += __shfl_xor_sync(0xffffffffu, s, 2);

    if ((c & 3) == 0) {
        float sc = mask[p] * phi[p] * 0.25f;   // 1/sqrt(16)
        g_alpha[(size_t)p * H + (c >> 2)] = s * sc;
    }
}

// ---------------------------------------------------------------------------
// Phase B: warp per destination node; lane owns features 2t,2t+1 (one half2).
// Whole V row = 128B = single wavefront. Unroll 4 for gather MLP.
// ---------------------------------------------------------------------------
__global__ __launch_bounds__(256)
void scatter_kernel(float* __restrict__ out, int n_nodes)
{
    int warp = (blockIdx.x * blockDim.x + threadIdx.x) >> 5;
    int lane = threadIdx.x & 31;
    if (warp >= n_nodes) return;

    int fo   = lane * 2;
    int head = lane >> 3;

    float2 acc = make_float2(0.f, 0.f);
    int s = g_start[warp];
    int e = g_start[warp + 1];

    int p = s;
    for (; p + 4 <= e; p += 4) {
        int   jj[4];
        float aa[4];
        float2 vv[4];
        #pragma unroll
        for (int u = 0; u < 4; u++) jj[u] = g_jj[p + u];
        #pragma unroll
        for (int u = 0; u < 4; u++) aa[u] = g_alpha[(size_t)(p + u) * H + head];
        #pragma unroll
        for (int u = 0; u < 4; u++)
            vv[u] = __half22float2(*(const __half2*)&g_Vh[(size_t)jj[u] * F + fo]);
        #pragma unroll
        for (int u = 0; u < 4; u++) {
            acc.x = fmaf(aa[u], vv[u].x, acc.x);
            acc.y = fmaf(aa[u], vv[u].y, acc.y);
        }
    }
    for (; p < e; p++) {
        int j = g_jj[p];
        float a = g_alpha[(size_t)p * H + head];
        float2 v = __half22float2(*(const __half2*)&g_Vh[(size_t)j * F + fo]);
        acc.x = fmaf(a, v.x, acc.x);
        acc.y = fmaf(a, v.y, acc.y);
    }

    *(float2*)&out[(size_t)warp * F + fo] = acc;
}

// ---------------------------------------------------------------------------
// Launch: x, w_ij, phi_r_cut, pair_mask, Wq, Wk, Wv, idx_i, idx_j
// ---------------------------------------------------------------------------
extern "C" void kernel_launch(void* const* d_in, const int* in_sizes, int n_in,
                              void* d_out, int out_size)
{
    const float* x     = (const float*)d_in[0];
    const float* w_ij  = (const float*)d_in[1];
    const float* phi   = (const float*)d_in[2];
    const float* mask  = (const float*)d_in[3];
    const float* Wq    = (const float*)d_in[4];
    const float* Wk    = (const float*)d_in[5];
    const float* Wv    = (const float*)d_in[6];
    const void*  idx_i = d_in[7];
    const void*  idx_j = d_in[8];
    float* out = (float*)d_out;

    int n_nodes = in_sizes[0] / F;
    int n_pairs = in_sizes[2];

    probe_kernel<<<1, 1>>>((const unsigned*)idx_j);

    conv_seg_kernel<<<(n_pairs + 255) / 256, 256>>>(idx_i, idx_j, n_pairs, n_nodes);

    proj_kernel<<<2048, 256>>>(x, Wq, Wk, Wv, n_nodes);

    int alpha_blocks = (n_pairs * 16 + 255) / 256;
    alpha_kernel<<<alpha_blocks, 256>>>(w_ij, phi, mask, n_pairs);

    scatter_kernel<<<(n_nodes + 7) / 8, 256>>>(out, n_nodes);
}

// round 5
// speedup vs baseline: 1.1860x; 1.0722x over previous
#include <cuda_runtime.h>
#include <cuda_fp16.h>
#include <stdint.h>

#define F 64
#define H 4
#define D 16
#define MAX_NODES 100000
#define MAX_PAIRS 1600000

__device__ float  g_Q[MAX_NODES * F];      // fp32: alpha gathers, no converts
__device__ float  g_K[MAX_NODES * F];
__device__ __half g_Vh[MAX_NODES * F];     // fp16: halves scatter gather traffic
__device__ float  g_alpha[MAX_PAIRS * H];
__device__ int    g_ii[MAX_PAIRS];
__device__ int    g_jj[MAX_PAIRS];
__device__ int    g_start[MAX_NODES + 1];
__device__ int    g_is64;

// ---------------------------------------------------------------------------
// Probe int64 vs int32 index layout (values < 2^31 => odd words zero if i64).
// ---------------------------------------------------------------------------
__global__ void probe_kernel(const unsigned* idxj_words) {
    bool is64 = true;
    #pragma unroll
    for (int i = 0; i < 16; i++)
        if (idxj_words[2 * i + 1] != 0u) is64 = false;
    g_is64 = is64 ? 1 : 0;
}

__device__ __forceinline__ int load_idx(const void* p, int i, bool is64) {
    if (is64) return (int)((const long long*)p)[i];
    return ((const int*)p)[i];
}

// ---------------------------------------------------------------------------
// Fused: idx -> int32 + segment starts from boundaries of sorted idx_i.
// ---------------------------------------------------------------------------
__global__ __launch_bounds__(256)
void conv_seg_kernel(const void* __restrict__ idx_i,
                     const void* __restrict__ idx_j,
                     int n_pairs, int n_nodes)
{
    int p = blockIdx.x * blockDim.x + threadIdx.x;
    if (p >= n_pairs) return;
    bool is64 = (g_is64 != 0);

    int ip = load_idx(idx_i, p, is64);
    int jp = load_idx(idx_j, p, is64);
    g_ii[p] = ip;
    g_jj[p] = jp;

    int prev = (p == 0) ? -1 : load_idx(idx_i, p - 1, is64);
    for (int n = prev + 1; n <= ip; n++) g_start[n] = p;
    if (p == n_pairs - 1)
        for (int n = ip + 1; n <= n_nodes; n++) g_start[n] = n_pairs;
}

// ---------------------------------------------------------------------------
// Projection: 4 nodes/block-iter, x staged in smem, W columns in registers.
// Q/K fp32, V fp16.
// ---------------------------------------------------------------------------
__global__ __launch_bounds__(256)
void proj_kernel(const float* __restrict__ x,
                 const float* __restrict__ Wq,
                 const float* __restrict__ Wk,
                 const float* __restrict__ Wv,
                 int n_nodes)
{
    __shared__ float xs[4 * F];
    int f   = threadIdx.x & 63;
    int row = threadIdx.x >> 6;
    int h   = f >> 4;
    int e   = f & 15;

    float wq[D], wk[D], wv[D];
    #pragma unroll
    for (int d = 0; d < D; d++) {
        wq[d] = Wq[h * D * D + d * D + e];
        wk[d] = Wk[h * D * D + d * D + e];
        wv[d] = Wv[h * D * D + d * D + e];
    }

    for (int base = blockIdx.x * 4; base < n_nodes; base += gridDim.x * 4) {
        __syncthreads();
        size_t gidx = (size_t)base * F + threadIdx.x;
        if (gidx < (size_t)n_nodes * F) xs[threadIdx.x] = x[gidx];
        __syncthreads();

        int n = base + row;
        if (n < n_nodes) {
            const float* xr = &xs[row * F + h * D];
            float q = 0.f, k = 0.f, v = 0.f;
            #pragma unroll
            for (int d = 0; d < D; d++) {
                float xv = xr[d];
                q = fmaf(xv, wq[d], q);
                k = fmaf(xv, wk[d], k);
                v = fmaf(xv, wv[d], v);
            }
            size_t o = (size_t)n * F + f;
            g_Q[o]  = q;
            g_K[o]  = k;
            g_Vh[o] = __float2half(v);
        }
    }
}

// ---------------------------------------------------------------------------
// Phase A: lane = (pair%2)*16 + chunk; each thread handles 4 pairs strided
// by n_pairs/4 -> 4 independent load/shfl chains, MLP ~12.
// ---------------------------------------------------------------------------
__global__ __launch_bounds__(256)
void alpha_kernel(const float* __restrict__ w_ij,
                  const float* __restrict__ phi,
                  const float* __restrict__ mask,
                  int n_pairs)
{
    int gid = blockIdx.x * blockDim.x + threadIdx.x;
    int c  = gid & 15;
    int p0 = gid >> 4;
    int quarter = n_pairs >> 2;          // n_pairs divisible by 4
    if (p0 >= quarter) return;

    int pp[4];
    #pragma unroll
    for (int u = 0; u < 4; u++) pp[u] = p0 + u * quarter;

    // batch idx + scale loads (independent)
    int ii[4], jj[4];
    float sc[4];
    #pragma unroll
    for (int u = 0; u < 4; u++) { ii[u] = g_ii[pp[u]]; jj[u] = g_jj[pp[u]]; }
    #pragma unroll
    for (int u = 0; u < 4; u++) sc[u] = mask[pp[u]] * phi[pp[u]] * 0.25f;

    // batch vector loads
    float4 w[4], q[4], k[4];
    #pragma unroll
    for (int u = 0; u < 4; u++)
        w[u] = __ldcs((const float4*)&w_ij[(size_t)pp[u] * F + c * 4]);
    #pragma unroll
    for (int u = 0; u < 4; u++)
        q[u] = *(const float4*)&g_Q[(size_t)ii[u] * F + c * 4];
    #pragma unroll
    for (int u = 0; u < 4; u++)
        k[u] = *(const float4*)&g_K[(size_t)jj[u] * F + c * 4];

    float s[4];
    #pragma unroll
    for (int u = 0; u < 4; u++) {
        float t = w[u].x * q[u].x * k[u].x;
        t = fmaf(w[u].y * q[u].y, k[u].y, t);
        t = fmaf(w[u].z * q[u].z, k[u].z, t);
        t = fmaf(w[u].w * q[u].w, k[u].w, t);
        s[u] = t;
    }

    // independent shuffle chains pipeline
    #pragma unroll
    for (int u = 0; u < 4; u++) s[u] += __shfl_xor_sync(0xffffffffu, s[u], 1);
    #pragma unroll
    for (int u = 0; u < 4; u++) s[u] += __shfl_xor_sync(0xffffffffu, s[u], 2);

    if ((c & 3) == 0) {
        int head = c >> 2;
        #pragma unroll
        for (int u = 0; u < 4; u++)
            g_alpha[(size_t)pp[u] * H + head] = s[u] * sc[u];
    }
}

// ---------------------------------------------------------------------------
// Phase B: warp per destination node; lane owns features 2t,2t+1 (one half2).
// Unroll 8 -> gather MLP ~8.
// ---------------------------------------------------------------------------
__global__ __launch_bounds__(256)
void scatter_kernel(float* __restrict__ out, int n_nodes)
{
    int warp = (blockIdx.x * blockDim.x + threadIdx.x) >> 5;
    int lane = threadIdx.x & 31;
    if (warp >= n_nodes) return;

    int fo   = lane * 2;
    int head = lane >> 3;

    float2 acc = make_float2(0.f, 0.f);
    int s = g_start[warp];
    int e = g_start[warp + 1];

    int p = s;
    for (; p + 8 <= e; p += 8) {
        int   jj[8];
        float aa[8];
        float2 vv[8];
        #pragma unroll
        for (int u = 0; u < 8; u++) jj[u] = g_jj[p + u];
        #pragma unroll
        for (int u = 0; u < 8; u++) aa[u] = g_alpha[(size_t)(p + u) * H + head];
        #pragma unroll
        for (int u = 0; u < 8; u++)
            vv[u] = __half22float2(*(const __half2*)&g_Vh[(size_t)jj[u] * F + fo]);
        #pragma unroll
        for (int u = 0; u < 8; u++) {
            acc.x = fmaf(aa[u], vv[u].x, acc.x);
            acc.y = fmaf(aa[u], vv[u].y, acc.y);
        }
    }
    for (; p < e; p++) {
        int j = g_jj[p];
        float a = g_alpha[(size_t)p * H + head];
        float2 v = __half22float2(*(const __half2*)&g_Vh[(size_t)j * F + fo]);
        acc.x = fmaf(a, v.x, acc.x);
        acc.y = fmaf(a, v.y, acc.y);
    }

    *(float2*)&out[(size_t)warp * F + fo] = acc;
}

// ---------------------------------------------------------------------------
// Launch: x, w_ij, phi_r_cut, pair_mask, Wq, Wk, Wv, idx_i, idx_j
// ---------------------------------------------------------------------------
extern "C" void kernel_launch(void* const* d_in, const int* in_sizes, int n_in,
                              void* d_out, int out_size)
{
    const float* x     = (const float*)d_in[0];
    const float* w_ij  = (const float*)d_in[1];
    const float* phi   = (const float*)d_in[2];
    const float* mask  = (const float*)d_in[3];
    const float* Wq    = (const float*)d_in[4];
    const float* Wk    = (const float*)d_in[5];
    const float* Wv    = (const float*)d_in[6];
    const void*  idx_i = d_in[7];
    const void*  idx_j = d_in[8];
    float* out = (float*)d_out;

    int n_nodes = in_sizes[0] / F;
    int n_pairs = in_sizes[2];

    probe_kernel<<<1, 1>>>((const unsigned*)idx_j);

    conv_seg_kernel<<<(n_pairs + 255) / 256, 256>>>(idx_i, idx_j, n_pairs, n_nodes);

    proj_kernel<<<2048, 256>>>(x, Wq, Wk, Wv, n_nodes);

    int quarter = n_pairs >> 2;
    int alpha_blocks = (quarter * 16 + 255) / 256;
    alpha_kernel<<<alpha_blocks, 256>>>(w_ij, phi, mask, n_pairs);

    scatter_kernel<<<(n_nodes + 7) / 8, 256>>>(out, n_nodes);
}

// round 6
// speedup vs baseline: 1.8725x; 1.5788x over previous
#include <cuda_runtime.h>
#include <cuda_fp16.h>
#include <stdint.h>

#define F 64
#define H 4
#define D 16
#define MAX_NODES 100000
#define MAX_PAIRS 1600000

// Q fp32 (loaded once per node); K,V packed fp16 per 4-feature chunk:
// row n (128 halves): chunk c in 0..15 -> [c*8 .. c*8+3] = K[4c..4c+3],
//                                         [c*8+4 .. c*8+7] = V[4c..4c+3]
__device__ float  g_Q[MAX_NODES * F];
__device__ __half g_KV[MAX_NODES * 2 * F];
__device__ int    g_jj[MAX_PAIRS];
__device__ int    g_start[MAX_NODES + 1];
__device__ int    g_is64;

// ---------------------------------------------------------------------------
// Probe int64 vs int32 index layout (values < 2^31 => odd words zero if i64).
// ---------------------------------------------------------------------------
__global__ void probe_kernel(const unsigned* idxj_words) {
    bool is64 = true;
    #pragma unroll
    for (int i = 0; i < 16; i++)
        if (idxj_words[2 * i + 1] != 0u) is64 = false;
    g_is64 = is64 ? 1 : 0;
}

__device__ __forceinline__ int load_idx(const void* p, int i, bool is64) {
    if (is64) return (int)((const long long*)p)[i];
    return ((const int*)p)[i];
}

// ---------------------------------------------------------------------------
// idx_j -> int32 + segment starts from boundaries of sorted idx_i.
// ---------------------------------------------------------------------------
__global__ __launch_bounds__(256)
void conv_seg_kernel(const void* __restrict__ idx_i,
                     const void* __restrict__ idx_j,
                     int n_pairs, int n_nodes)
{
    int p = blockIdx.x * blockDim.x + threadIdx.x;
    if (p >= n_pairs) return;
    bool is64 = (g_is64 != 0);

    int ip = load_idx(idx_i, p, is64);
    g_jj[p] = load_idx(idx_j, p, is64);

    int prev = (p == 0) ? -1 : load_idx(idx_i, p - 1, is64);
    for (int n = prev + 1; n <= ip; n++) g_start[n] = p;
    if (p == n_pairs - 1)
        for (int n = ip + 1; n <= n_nodes; n++) g_start[n] = n_pairs;
}

// ---------------------------------------------------------------------------
// Projection: 4 nodes/block-iter, x staged in smem, W columns in registers.
// Writes Q fp32 and chunk-interleaved fp16 KV.
// ---------------------------------------------------------------------------
__global__ __launch_bounds__(256)
void proj_kernel(const float* __restrict__ x,
                 const float* __restrict__ Wq,
                 const float* __restrict__ Wk,
                 const float* __restrict__ Wv,
                 int n_nodes)
{
    __shared__ float xs[4 * F];
    int f   = threadIdx.x & 63;   // h*16 + e
    int row = threadIdx.x >> 6;
    int h   = f >> 4;
    int e   = f & 15;
    int c   = f >> 2;             // 4-feature chunk
    int r   = f & 3;

    float wq[D], wk[D], wv[D];
    #pragma unroll
    for (int d = 0; d < D; d++) {
        wq[d] = Wq[h * D * D + d * D + e];
        wk[d] = Wk[h * D * D + d * D + e];
        wv[d] = Wv[h * D * D + d * D + e];
    }

    for (int base = blockIdx.x * 4; base < n_nodes; base += gridDim.x * 4) {
        __syncthreads();
        size_t gidx = (size_t)base * F + threadIdx.x;
        if (gidx < (size_t)n_nodes * F) xs[threadIdx.x] = x[gidx];
        __syncthreads();

        int n = base + row;
        if (n < n_nodes) {
            const float* xr = &xs[row * F + h * D];
            float q = 0.f, k = 0.f, v = 0.f;
            #pragma unroll
            for (int d = 0; d < D; d++) {
                float xv = xr[d];
                q = fmaf(xv, wq[d], q);
                k = fmaf(xv, wk[d], k);
                v = fmaf(xv, wv[d], v);
            }
            g_Q[(size_t)n * F + f] = q;
            size_t kvb = (size_t)n * 2 * F + c * 8;
            g_KV[kvb + r]     = __float2half(k);
            g_KV[kvb + 4 + r] = __float2half(v);
        }
    }
}

// ---------------------------------------------------------------------------
// Fused alpha+scatter: warp per node. lane = half*16 + c; half = pair parity,
// chunk c owns features 4c..4c+3 (head c>>2). Per pair: one float4 w load,
// ONE uint4 KV gather, 2 shfls for the head dot, fma into per-lane acc.
// Cross-half reduce + coalesced float4 store at the end.
// ---------------------------------------------------------------------------
__global__ __launch_bounds__(256)
void fused_kernel(const float* __restrict__ w_ij,
                  const float* __restrict__ phi,
                  const float* __restrict__ mask,
                  float* __restrict__ out,
                  int n_nodes)
{
    int node = (blockIdx.x * blockDim.x + threadIdx.x) >> 5;
    int lane = threadIdx.x & 31;
    if (node >= n_nodes) return;

    int half = lane >> 4;
    int c    = lane & 15;

    float4 q = *(const float4*)&g_Q[(size_t)node * F + c * 4];
    float4 acc = make_float4(0.f, 0.f, 0.f, 0.f);

    int s = g_start[node];
    int e = g_start[node + 1];

    int p = s;
    // main loop: 2 duos (4 pairs) per iteration, batched loads
    for (; p + 4 <= e; p += 4) {
        int pa0 = p + half;
        int pa1 = p + 2 + half;
        int j0 = g_jj[pa0];
        int j1 = g_jj[pa1];
        float sc0 = mask[pa0] * phi[pa0] * 0.25f;
        float sc1 = mask[pa1] * phi[pa1] * 0.25f;
        float4 w0 = __ldcs((const float4*)&w_ij[(size_t)pa0 * F + c * 4]);
        float4 w1 = __ldcs((const float4*)&w_ij[(size_t)pa1 * F + c * 4]);
        uint4 kv0 = *(const uint4*)&g_KV[(size_t)j0 * 2 * F + c * 8];
        uint4 kv1 = *(const uint4*)&g_KV[(size_t)j1 * 2 * F + c * 8];

        float2 k00 = __half22float2(*(const __half2*)&kv0.x);
        float2 k01 = __half22float2(*(const __half2*)&kv0.y);
        float2 k10 = __half22float2(*(const __half2*)&kv1.x);
        float2 k11 = __half22float2(*(const __half2*)&kv1.y);

        float t0 = w0.x * q.x * k00.x;
        t0 = fmaf(w0.y * q.y, k00.y, t0);
        t0 = fmaf(w0.z * q.z, k01.x, t0);
        t0 = fmaf(w0.w * q.w, k01.y, t0);
        float t1 = w1.x * q.x * k10.x;
        t1 = fmaf(w1.y * q.y, k10.y, t1);
        t1 = fmaf(w1.z * q.z, k11.x, t1);
        t1 = fmaf(w1.w * q.w, k11.y, t1);

        t0 += __shfl_xor_sync(0xffffffffu, t0, 1);
        t1 += __shfl_xor_sync(0xffffffffu, t1, 1);
        t0 += __shfl_xor_sync(0xffffffffu, t0, 2);
        t1 += __shfl_xor_sync(0xffffffffu, t1, 2);

        float a0 = t0 * sc0;
        float a1 = t1 * sc1;

        float2 v00 = __half22float2(*(const __half2*)&kv0.z);
        float2 v01 = __half22float2(*(const __half2*)&kv0.w);
        float2 v10 = __half22float2(*(const __half2*)&kv1.z);
        float2 v11 = __half22float2(*(const __half2*)&kv1.w);

        acc.x = fmaf(a0, v00.x, acc.x);
        acc.y = fmaf(a0, v00.y, acc.y);
        acc.z = fmaf(a0, v01.x, acc.z);
        acc.w = fmaf(a0, v01.y, acc.w);
        acc.x = fmaf(a1, v10.x, acc.x);
        acc.y = fmaf(a1, v10.y, acc.y);
        acc.z = fmaf(a1, v11.x, acc.z);
        acc.w = fmaf(a1, v11.y, acc.w);
    }
    // remainder: one duo at a time, clamped
    for (; p < e; p += 2) {
        int pa = p + half;
        int pv = (pa < e) ? pa : (e - 1);
        float scl = (pa < e) ? (mask[pv] * phi[pv] * 0.25f) : 0.f;
        int j = g_jj[pv];
        float4 w = __ldcs((const float4*)&w_ij[(size_t)pv * F + c * 4]);
        uint4 kv = *(const uint4*)&g_KV[(size_t)j * 2 * F + c * 8];

        float2 k0 = __half22float2(*(const __half2*)&kv.x);
        float2 k1 = __half22float2(*(const __half2*)&kv.y);
        float t = w.x * q.x * k0.x;
        t = fmaf(w.y * q.y, k0.y, t);
        t = fmaf(w.z * q.z, k1.x, t);
        t = fmaf(w.w * q.w, k1.y, t);
        t += __shfl_xor_sync(0xffffffffu, t, 1);
        t += __shfl_xor_sync(0xffffffffu, t, 2);
        float a = t * scl;
        float2 v0 = __half22float2(*(const __half2*)&kv.z);
        float2 v1 = __half22float2(*(const __half2*)&kv.w);
        acc.x = fmaf(a, v0.x, acc.x);
        acc.y = fmaf(a, v0.y, acc.y);
        acc.z = fmaf(a, v1.x, acc.z);
        acc.w = fmaf(a, v1.y, acc.w);
    }

    // combine the two halves and store
    acc.x += __shfl_xor_sync(0xffffffffu, acc.x, 16);
    acc.y += __shfl_xor_sync(0xffffffffu, acc.y, 16);
    acc.z += __shfl_xor_sync(0xffffffffu, acc.z, 16);
    acc.w += __shfl_xor_sync(0xffffffffu, acc.w, 16);

    if (half == 0)
        *(float4*)&out[(size_t)node * F + c * 4] = acc;
}

// ---------------------------------------------------------------------------
// Launch: x, w_ij, phi_r_cut, pair_mask, Wq, Wk, Wv, idx_i, idx_j
// ---------------------------------------------------------------------------
extern "C" void kernel_launch(void* const* d_in, const int* in_sizes, int n_in,
                              void* d_out, int out_size)
{
    const float* x     = (const float*)d_in[0];
    const float* w_ij  = (const float*)d_in[1];
    const float* phi   = (const float*)d_in[2];
    const float* mask  = (const float*)d_in[3];
    const float* Wq    = (const float*)d_in[4];
    const float* Wk    = (const float*)d_in[5];
    const float* Wv    = (const float*)d_in[6];
    const void*  idx_i = d_in[7];
    const void*  idx_j = d_in[8];
    float* out = (float*)d_out;

    int n_nodes = in_sizes[0] / F;
    int n_pairs = in_sizes[2];

    probe_kernel<<<1, 1>>>((const unsigned*)idx_j);

    conv_seg_kernel<<<(n_pairs + 255) / 256, 256>>>(idx_i, idx_j, n_pairs, n_nodes);

    proj_kernel<<<2048, 256>>>(x, Wq, Wk, Wv, n_nodes);

    fused_kernel<<<(n_nodes + 7) / 8, 256>>>(w_ij, phi, mask, out, n_nodes);
}